// round 13
// baseline (speedup 1.0000x reference)
#include <cuda_runtime.h>
#include <cuda_bf16.h>
#include <cuda_fp16.h>
#include <math.h>

#define NN 100000
#define EE 6400000
#define IN_CH 128
#define TILE 512
#define NB ((NN + TILE - 1) / TILE)   // 196

__device__ __forceinline__ unsigned h2u(__half2 h) { return *reinterpret_cast<unsigned*>(&h); }
__device__ __forceinline__ __half2 u2h(unsigned u) { return *reinterpret_cast<__half2*>(&u); }
__device__ __forceinline__ float lrelu(float v) { return v > 0.f ? v : 0.2f * v; }

// ---------------- scratch (static device memory; zero-initialized) -----------
__device__ __align__(32) unsigned g_rec1[NN * 8];  // {as0,as1 f32, h01..h89 half2, pad}
__device__ __align__(32) unsigned g_rec2[NN * 8];  // {as f32, h01..h89 half2, pad x2}
__device__ __align__(16) float g_W1T[10][IN_CH];   // transposed W1
__device__ __align__(16) float g_ad1[NN * 2];
__device__ __align__(16) float g_t1[NN * 10];
__device__ float g_ad2[NN];
__device__ double g_bnsum[10];       // zeroed at tail of kedge2
__device__ double g_bnsumsq[10];
__device__ int g_deg[NN];            // zeroed at tail of kedge2
__device__ int g_rowstart[NN + 1];   // per-tile-local exclusive scan
__device__ int g_rank[EE];           // edge rank within its dst (from khist)
__device__ int g_ssrc[EE];
__device__ int g_partial[NB];
__device__ int g_tileoff[NB];
__device__ int g_is64;

// ---------------- khist: dst histogram + rank capture + dtype vote ------------
__global__ void khist(const void* __restrict__ ei) {
    __shared__ int s_is64;
    const int* ip = (const int*)ei;
    if (threadIdx.x == 0) {
        int zeros = 0;
        for (int k = 0; k < 64; k++) zeros += (ip[2 * k + 1] == 0);
        s_is64 = (zeros >= 32);
        if (blockIdx.x == 0) g_is64 = s_is64;
    }
    __syncthreads();
    int gtid = blockIdx.x * 256 + threadIdx.x;   // 12500x256 = EE/2 exact
    int d0, d1;
    if (s_is64) {
        int4 v = ((const int4*)ip)[EE / 2 + gtid];
        d0 = v.x; d1 = v.z;
    } else {
        int2 v = ((const int2*)ip)[EE / 2 + gtid];
        d0 = v.x; d1 = v.y;
    }
    int r0 = atomicAdd(&g_deg[d0], 1);
    int r1 = atomicAdd(&g_deg[d1], 1);
    ((int2*)g_rank)[gtid] = make_int2(r0, r1);
}

// ---------------- ktrans: W1 [128][10] -> W1T [10][128] ------------------------
__global__ void ktrans(const float* __restrict__ W1) {
    int idx = blockIdx.x * blockDim.x + threadIdx.x;
    if (idx < 10 * IN_CH) {
        int j = idx / IN_CH;
        int k = idx - j * IN_CH;
        g_W1T[j][k] = W1[k * 10 + j];
    }
}

// ---------------- kscan1: per-tile exclusive scan ------------------------------
__global__ void kscan1() {
    __shared__ int s[TILE];
    int b = blockIdx.x, t = threadIdx.x;
    int i = b * TILE + t;
    int v = (i < NN) ? g_deg[i] : 0;
    s[t] = v;
    __syncthreads();
#pragma unroll
    for (int o = 1; o < TILE; o <<= 1) {
        int u = (t >= o) ? s[t - o] : 0;
        __syncthreads();
        s[t] += u;
        __syncthreads();
    }
    if (i <= NN) g_rowstart[i] = s[t] - v;   // includes boundary i==NN
    if (t == TILE - 1) g_partial[b] = s[t];
}

// ---------------- kscan2: tile offsets -----------------------------------------
__global__ void kscan2() {
    __shared__ int s[256];
    int t = threadIdx.x;
    int v = (t < NB) ? g_partial[t] : 0;
    s[t] = v;
    __syncthreads();
#pragma unroll
    for (int o = 1; o < 256; o <<= 1) {
        int u = (t >= o) ? s[t - o] : 0;
        __syncthreads();
        s[t] += u;
        __syncthreads();
    }
    if (t < NB) g_tileoff[t] = s[t] - v;
}

// ---------------- kscatter: atomic-free placement ------------------------------
__global__ void kscatter(const void* __restrict__ ei) {
    int gtid = blockIdx.x * 256 + threadIdx.x;
    const int* ip = (const int*)ei;
    int s0, s1, d0, d1;
    if (g_is64) {
        int4 sv = ((const int4*)ip)[gtid];
        int4 dv = ((const int4*)ip)[EE / 2 + gtid];
        s0 = sv.x; s1 = sv.z; d0 = dv.x; d1 = dv.z;
    } else {
        int2 sv = ((const int2*)ip)[gtid];
        int2 dv = ((const int2*)ip)[EE / 2 + gtid];
        s0 = sv.x; s1 = sv.y; d0 = dv.x; d1 = dv.y;
    }
    int2 rk = ((const int2*)g_rank)[gtid];
    int p0 = g_rowstart[d0] + g_tileoff[d0 >> 9] + rk.x;
    g_ssrc[p0] = s0;
    int p1 = g_rowstart[d1] + g_tileoff[d1 >> 9] + rk.y;
    g_ssrc[p1] = s1;
}

// ---------------- k1: layer1 node GEMM (4 nodes per warp, W in regs) -----------
__global__ void __launch_bounds__(256) k1(const float* __restrict__ x,
                                          const float* __restrict__ a1s,
                                          const float* __restrict__ a1d) {
    int lane = threadIdx.x & 31;
    int warp = (blockIdx.x * 256 + threadIdx.x) >> 5;   // 3125 blocks -> 25000 warps
    int node0 = warp * 4;

    float4 w[10];
#pragma unroll
    for (int j = 0; j < 10; j++)
        w[j] = *(const float4*)(&g_W1T[j][lane * 4]);

#pragma unroll
    for (int n = 0; n < 4; n++) {
        int node = node0 + n;
        float4 xv = *(const float4*)(x + (size_t)node * IN_CH + lane * 4);
        float acc[10];
#pragma unroll
        for (int j = 0; j < 10; j++)
            acc[j] = xv.x * w[j].x + xv.y * w[j].y + xv.z * w[j].z + xv.w * w[j].w;
#pragma unroll
        for (int j = 0; j < 10; j++)
#pragma unroll
            for (int o = 16; o; o >>= 1)
                acc[j] += __shfl_xor_sync(0xffffffffu, acc[j], o);

        if (lane == 0) {
            float as0 = 0.f, as1v = 0.f, ad0 = 0.f, ad1v = 0.f;
#pragma unroll
            for (int c = 0; c < 5; c++) {
                as0  += acc[c]     * a1s[c];
                as1v += acc[5 + c] * a1s[5 + c];
                ad0  += acc[c]     * a1d[c];
                ad1v += acc[5 + c] * a1d[5 + c];
            }
            ((float2*)g_ad1)[node] = make_float2(ad0, ad1v);
            uint4 a, b;
            a.x = __float_as_uint(as0);
            a.y = __float_as_uint(as1v);
            a.z = h2u(__floats2half2_rn(acc[0], acc[1]));
            a.w = h2u(__floats2half2_rn(acc[2], acc[3]));
            b.x = h2u(__floats2half2_rn(acc[4], acc[5]));
            b.y = h2u(__floats2half2_rn(acc[6], acc[7]));
            b.z = h2u(__floats2half2_rn(acc[8], acc[9]));
            b.w = 0u;
            uint4* rp = (uint4*)(g_rec1 + (size_t)node * 8);
            rp[0] = a;
            rp[1] = b;
        }
    }
}

// ---------------- kedge1: lane-pair gather, 4 loads in flight ------------------
__device__ __forceinline__ void acc1_even(float acc[12], uint4 v, float x0, float x1) {
    float2 f01 = __half22float2(u2h(v.z));
    float2 f23 = __half22float2(u2h(v.w));
    acc[0] += x0;         acc[1] += x1;
    acc[2] += x0 * f01.x; acc[3] += x0 * f01.y;
    acc[4] += x0 * f23.x; acc[5] += x0 * f23.y;
}
__device__ __forceinline__ void acc1_odd(float acc[12], uint4 v, float x0, float x1) {
    float2 f45 = __half22float2(u2h(v.x));
    float2 f67 = __half22float2(u2h(v.y));
    float2 f89 = __half22float2(u2h(v.z));
    acc[6] += x0 * f45.x;  acc[7] += x1 * f45.y;
    acc[8] += x1 * f67.x;  acc[9] += x1 * f67.y;
    acc[10] += x1 * f89.x; acc[11] += x1 * f89.y;
}

__global__ void kedge1(const float* __restrict__ b1) {
    int lane = threadIdx.x & 31;
    int pairIdx = lane >> 1;
    int isOdd = lane & 1;
    int d = (blockIdx.x * 256 + threadIdx.x) >> 5;   // < NN exactly
    int rs = g_rowstart[d] + g_tileoff[d >> 9];
    int re = g_rowstart[d + 1] + g_tileoff[(d + 1) >> 9];
    float2 ad = ((const float2*)g_ad1)[d];

    float acc[12];
#pragma unroll
    for (int j = 0; j < 12; j++) acc[j] = 0.f;

    // virtual self-loop at rs-1; 64 edges per warp step, 4 loads in flight
    for (int base = rs - 1; base < re; base += 64) {
        int jj[4];
        bool ok[4];
        int ss[4];
#pragma unroll
        for (int q = 0; q < 4; q++) {
            jj[q] = base + pairIdx + q * 16;
            ok[q] = (jj[q] < re);
            ss[q] = (ok[q] && jj[q] >= rs) ? g_ssrc[jj[q]] : d;
        }
        uint4 v[4];
#pragma unroll
        for (int q = 0; q < 4; q++)
            v[q] = ((const uint4*)(g_rec1 + (size_t)ss[q] * 8))[isOdd];
        float x0[4], x1[4];
#pragma unroll
        for (int q = 0; q < 4; q++) {
            x0[q] = __expf(lrelu(__uint_as_float(v[q].x) + ad.x));
            x1[q] = __expf(lrelu(__uint_as_float(v[q].y) + ad.y));
        }
#pragma unroll
        for (int q = 0; q < 4; q++) {
            x0[q] = __shfl_sync(0xffffffffu, x0[q], lane & ~1);
            x1[q] = __shfl_sync(0xffffffffu, x1[q], lane & ~1);
        }
#pragma unroll
        for (int q = 0; q < 4; q++) {
            if (ok[q]) {
                if (!isOdd) acc1_even(acc, v[q], x0[q], x1[q]);
                else        acc1_odd(acc, v[q], x0[q], x1[q]);
            }
        }
    }
#pragma unroll
    for (int k = 0; k < 12; k++)
#pragma unroll
        for (int o = 16; o; o >>= 1)
            acc[k] += __shfl_xor_sync(0xffffffffu, acc[k], o);

    if (lane == 0) {
        float i0 = 1.f / (acc[0] + 1e-16f);
        float i1 = 1.f / (acc[1] + 1e-16f);
        float2* tp = (float2*)(g_t1 + (size_t)d * 10);
        tp[0] = make_float2(acc[2] * i0 + b1[0], acc[3] * i0 + b1[1]);
        tp[1] = make_float2(acc[4] * i0 + b1[2], acc[5] * i0 + b1[3]);
        tp[2] = make_float2(acc[6] * i0 + b1[4], acc[7] * i1 + b1[5]);
        tp[3] = make_float2(acc[8] * i1 + b1[6], acc[9] * i1 + b1[7]);
        tp[4] = make_float2(acc[10] * i1 + b1[8], acc[11] * i1 + b1[9]);
    }
}

// ---------------- kbn: BN statistics -------------------------------------------
__global__ void kbn() {
    __shared__ double ssum[10], ssq[10];
    if (threadIdx.x < 10) { ssum[threadIdx.x] = 0.0; ssq[threadIdx.x] = 0.0; }
    __syncthreads();
    int node = blockIdx.x * blockDim.x + threadIdx.x;
    int lane = threadIdx.x & 31;
    float t[10];
    if (node < NN) {
        const float2* tp = (const float2*)(g_t1 + (size_t)node * 10);
#pragma unroll
        for (int c = 0; c < 5; c++) {
            float2 v = tp[c];
            t[2 * c] = v.x;
            t[2 * c + 1] = v.y;
        }
    } else {
#pragma unroll
        for (int j = 0; j < 10; j++) t[j] = 0.f;
    }
#pragma unroll
    for (int j = 0; j < 10; j++) {
        float v = t[j];
        float s = t[j] * t[j];
#pragma unroll
        for (int o = 16; o; o >>= 1) {
            v += __shfl_xor_sync(0xffffffffu, v, o);
            s += __shfl_xor_sync(0xffffffffu, s, o);
        }
        if (lane == 0) {
            atomicAdd(&ssum[j], (double)v);
            atomicAdd(&ssq[j], (double)s);
        }
    }
    __syncthreads();
    if (threadIdx.x < 10) {
        atomicAdd(&g_bnsum[threadIdx.x], ssum[threadIdx.x]);
        atomicAdd(&g_bnsumsq[threadIdx.x], ssq[threadIdx.x]);
    }
}

// ---------------- k5: BN const + apply + ELU + layer2 node GEMM ----------------
__global__ void k5(const float* __restrict__ W2, const float* __restrict__ a2s,
                   const float* __restrict__ a2d, const float* __restrict__ gamma,
                   const float* __restrict__ beta) {
    __shared__ float sW[100], sa[10], sd[10], ssc[10], ssh[10];
    if (threadIdx.x < 100) sW[threadIdx.x] = W2[threadIdx.x];
    if (threadIdx.x < 10) {
        sa[threadIdx.x] = a2s[threadIdx.x];
        sd[threadIdx.x] = a2d[threadIdx.x];
        double mean = g_bnsum[threadIdx.x] / (double)NN;
        double var = g_bnsumsq[threadIdx.x] / (double)NN - mean * mean;
        float sc = gamma[threadIdx.x] * (float)rsqrt(var + 1e-5);
        ssc[threadIdx.x] = sc;
        ssh[threadIdx.x] = beta[threadIdx.x] - (float)mean * sc;
    }
    __syncthreads();
    int node = blockIdx.x * blockDim.x + threadIdx.x;
    if (node >= NN) return;

    float y[10];
    const float2* tp = (const float2*)(g_t1 + (size_t)node * 10);
#pragma unroll
    for (int c = 0; c < 5; c++) {
        float2 v = tp[c];
        float u0 = v.x * ssc[2 * c] + ssh[2 * c];
        float u1 = v.y * ssc[2 * c + 1] + ssh[2 * c + 1];
        y[2 * c]     = u0 > 0.f ? u0 : expm1f(u0);
        y[2 * c + 1] = u1 > 0.f ? u1 : expm1f(u1);
    }
    float h[10];
#pragma unroll
    for (int c = 0; c < 10; c++) {
        float s = 0.f;
#pragma unroll
        for (int jj = 0; jj < 10; jj++) s += y[jj] * sW[jj * 10 + c];
        h[c] = s;
    }
    float as = 0.f, ad = 0.f;
#pragma unroll
    for (int c = 0; c < 10; c++) {
        as += h[c] * sa[c];
        ad += h[c] * sd[c];
    }
    g_ad2[node] = ad;
    uint4 a, b;
    a.x = __float_as_uint(as);
    a.y = h2u(__floats2half2_rn(h[0], h[1]));
    a.z = h2u(__floats2half2_rn(h[2], h[3]));
    a.w = h2u(__floats2half2_rn(h[4], h[5]));
    b.x = h2u(__floats2half2_rn(h[6], h[7]));
    b.y = h2u(__floats2half2_rn(h[8], h[9]));
    b.z = 0u; b.w = 0u;
    uint4* rp = (uint4*)(g_rec2 + (size_t)node * 8);
    rp[0] = a;
    rp[1] = b;
}

// ---------------- kedge2: lane-pair gather, 4 loads in flight -> output --------
__device__ __forceinline__ void acc2_even(float acc[11], uint4 v, float ex) {
    float2 f01 = __half22float2(u2h(v.y));
    float2 f23 = __half22float2(u2h(v.z));
    float2 f45 = __half22float2(u2h(v.w));
    acc[0] += ex;
    acc[1] += ex * f01.x; acc[2] += ex * f01.y;
    acc[3] += ex * f23.x; acc[4] += ex * f23.y;
    acc[5] += ex * f45.x; acc[6] += ex * f45.y;
}
__device__ __forceinline__ void acc2_odd(float acc[11], uint4 v, float ex) {
    float2 f67 = __half22float2(u2h(v.x));
    float2 f89 = __half22float2(u2h(v.y));
    acc[7] += ex * f67.x; acc[8] += ex * f67.y;
    acc[9] += ex * f89.x; acc[10] += ex * f89.y;
}

__global__ void kedge2(float* __restrict__ out, const float* __restrict__ b2) {
    int gtid = blockIdx.x * 256 + threadIdx.x;
    if (gtid < NN) g_deg[gtid] = 0;
    if (gtid < 10) g_bnsum[gtid] = 0.0;
    else if (gtid < 20) g_bnsumsq[gtid - 10] = 0.0;

    int lane = threadIdx.x & 31;
    int pairIdx = lane >> 1;
    int isOdd = lane & 1;
    int d = gtid >> 5;
    int rs = g_rowstart[d] + g_tileoff[d >> 9];
    int re = g_rowstart[d + 1] + g_tileoff[(d + 1) >> 9];
    float ad = g_ad2[d];

    float acc[11];
#pragma unroll
    for (int j = 0; j < 11; j++) acc[j] = 0.f;

    for (int base = rs - 1; base < re; base += 64) {
        int jj[4];
        bool ok[4];
        int ss[4];
#pragma unroll
        for (int q = 0; q < 4; q++) {
            jj[q] = base + pairIdx + q * 16;
            ok[q] = (jj[q] < re);
            ss[q] = (ok[q] && jj[q] >= rs) ? g_ssrc[jj[q]] : d;
        }
        uint4 v[4];
#pragma unroll
        for (int q = 0; q < 4; q++)
            v[q] = ((const uint4*)(g_rec2 + (size_t)ss[q] * 8))[isOdd];
        float ex[4];
#pragma unroll
        for (int q = 0; q < 4; q++)
            ex[q] = __expf(lrelu(__uint_as_float(v[q].x) + ad));
#pragma unroll
        for (int q = 0; q < 4; q++)
            ex[q] = __shfl_sync(0xffffffffu, ex[q], lane & ~1);
#pragma unroll
        for (int q = 0; q < 4; q++) {
            if (ok[q]) {
                if (!isOdd) acc2_even(acc, v[q], ex[q]);
                else        acc2_odd(acc, v[q], ex[q]);
            }
        }
    }
#pragma unroll
    for (int k = 0; k < 11; k++)
#pragma unroll
        for (int o = 16; o; o >>= 1)
            acc[k] += __shfl_xor_sync(0xffffffffu, acc[k], o);

    if (lane == 0) {
        float inv = 1.f / (acc[0] + 1e-16f);
        float* op = out + (size_t)d * 10;
#pragma unroll
        for (int c = 0; c < 10; c++)
            op[c] = acc[1 + c] * inv + b2[c];
    }
}

// ---------------- launch ---------------------------------------------------------
extern "C" void kernel_launch(void* const* d_in, const int* in_sizes, int n_in,
                              void* d_out, int out_size) {
    (void)in_sizes; (void)n_in; (void)out_size;
    const float* x      = (const float*)d_in[0];
    const float* W1     = (const float*)d_in[1];
    const float* a_src1 = (const float*)d_in[2];
    const float* a_dst1 = (const float*)d_in[3];
    const float* b1     = (const float*)d_in[4];
    const float* gamma1 = (const float*)d_in[5];
    const float* beta1  = (const float*)d_in[6];
    const float* W2     = (const float*)d_in[7];
    const float* a_src2 = (const float*)d_in[8];
    const float* a_dst2 = (const float*)d_in[9];
    const float* b2     = (const float*)d_in[10];
    const void*  ei     = d_in[11];

    khist<<<12500, 256>>>(ei);                                        // 0
    kscan1<<<NB, TILE>>>();                                           // 1
    kscan2<<<1, 256>>>();                                             // 2
    kscatter<<<12500, 256>>>(ei);                                     // 3 <- profiled
    ktrans<<<5, 256>>>(W1);                                           // 4
    k1<<<3125, 256>>>(x, a_src1, a_dst1);                             // 5
    kedge1<<<12500, 256>>>(b1);                                       // 6
    kbn<<<(NN + 255) / 256, 256>>>();                                 // 7
    k5<<<(NN + 255) / 256, 256>>>(W2, a_src2, a_dst2, gamma1, beta1); // 8
    kedge2<<<12500, 256>>>((float*)d_out, b2);                        // 9
}

// round 14
// speedup vs baseline: 1.0502x; 1.0502x over previous
#include <cuda_runtime.h>
#include <cuda_bf16.h>
#include <cuda_fp16.h>
#include <math.h>

#define NN 100000
#define EE 6400000
#define IN_CH 128
#define TILE 512
#define NB ((NN + TILE - 1) / TILE)   // 196

__device__ __forceinline__ unsigned h2u(__half2 h) { return *reinterpret_cast<unsigned*>(&h); }
__device__ __forceinline__ __half2 u2h(unsigned u) { return *reinterpret_cast<__half2*>(&u); }
__device__ __forceinline__ float lrelu(float v) { return v > 0.f ? v : 0.2f * v; }

// ---------------- scratch (static device memory; zero-initialized) -----------
__device__ __align__(32) unsigned g_rec1[NN * 8];  // {as0,as1 f32, h01..h89 half2, pad}
__device__ __align__(32) unsigned g_rec2[NN * 8];  // {as f32, h01..h89 half2, pad x2}
__device__ __align__(16) float g_W1T[10][IN_CH];   // transposed W1
__device__ __align__(16) float g_ad1[NN * 2];
__device__ __align__(16) float g_t1[NN * 10];
__device__ float g_ad2[NN];
__device__ double g_bnsum[10];       // zeroed at tail of kedge2
__device__ double g_bnsumsq[10];
__device__ int g_deg[NN];            // zeroed at tail of kedge2
__device__ int g_rowstart[NN + 1];   // per-tile-local exclusive scan
__device__ int g_rank[EE];           // edge rank within its dst (from khist)
__device__ int g_ssrc[EE];
__device__ int g_partial[NB];
__device__ int g_tileoff[NB];
__device__ int g_is64;

// ---------------- khist: dst histogram + rank capture + W1 transpose ----------
__global__ void khist(const void* __restrict__ ei, const float* __restrict__ W1) {
    __shared__ int s_is64;
    const int* ip = (const int*)ei;
    if (threadIdx.x == 0) {
        int zeros = 0;
        for (int k = 0; k < 64; k++) zeros += (ip[2 * k + 1] == 0);
        s_is64 = (zeros >= 32);
        if (blockIdx.x == 0) g_is64 = s_is64;
    }
    // fused W1 transpose on first 5 blocks (result used later by k1)
    if (blockIdx.x < 5) {
        int idx = blockIdx.x * 256 + threadIdx.x;
        if (idx < 10 * IN_CH) {
            int j = idx / IN_CH;
            int k = idx - j * IN_CH;
            g_W1T[j][k] = W1[k * 10 + j];
        }
    }
    __syncthreads();
    int gtid = blockIdx.x * 256 + threadIdx.x;   // 12500x256 = EE/2 exact
    int d0, d1;
    if (s_is64) {
        int4 v = __ldcs(&((const int4*)ip)[EE / 2 + gtid]);
        d0 = v.x; d1 = v.z;
    } else {
        int2 v = __ldcs(&((const int2*)ip)[EE / 2 + gtid]);
        d0 = v.x; d1 = v.y;
    }
    int r0 = atomicAdd(&g_deg[d0], 1);
    int r1 = atomicAdd(&g_deg[d1], 1);
    __stcs(&((int2*)g_rank)[gtid], make_int2(r0, r1));
}

// ---------------- kscan1: per-tile exclusive scan ------------------------------
__global__ void kscan1() {
    __shared__ int s[TILE];
    int b = blockIdx.x, t = threadIdx.x;
    int i = b * TILE + t;
    int v = (i < NN) ? g_deg[i] : 0;
    s[t] = v;
    __syncthreads();
#pragma unroll
    for (int o = 1; o < TILE; o <<= 1) {
        int u = (t >= o) ? s[t - o] : 0;
        __syncthreads();
        s[t] += u;
        __syncthreads();
    }
    if (i <= NN) g_rowstart[i] = s[t] - v;   // includes boundary i==NN
    if (t == TILE - 1) g_partial[b] = s[t];
}

// ---------------- kscan2: tile offsets -----------------------------------------
__global__ void kscan2() {
    __shared__ int s[256];
    int t = threadIdx.x;
    int v = (t < NB) ? g_partial[t] : 0;
    s[t] = v;
    __syncthreads();
#pragma unroll
    for (int o = 1; o < 256; o <<= 1) {
        int u = (t >= o) ? s[t - o] : 0;
        __syncthreads();
        s[t] += u;
        __syncthreads();
    }
    if (t < NB) g_tileoff[t] = s[t] - v;
}

// ---------------- kscatter: atomic-free placement, streaming hints -------------
__global__ void kscatter(const void* __restrict__ ei) {
    int gtid = blockIdx.x * 256 + threadIdx.x;
    const int* ip = (const int*)ei;
    int s0, s1, d0, d1;
    if (g_is64) {
        int4 sv = __ldcs(&((const int4*)ip)[gtid]);
        int4 dv = __ldcs(&((const int4*)ip)[EE / 2 + gtid]);
        s0 = sv.x; s1 = sv.z; d0 = dv.x; d1 = dv.z;
    } else {
        int2 sv = __ldcs(&((const int2*)ip)[gtid]);
        int2 dv = __ldcs(&((const int2*)ip)[EE / 2 + gtid]);
        s0 = sv.x; s1 = sv.y; d0 = dv.x; d1 = dv.y;
    }
    int2 rk = __ldcs(&((const int2*)g_rank)[gtid]);
    int p0 = g_rowstart[d0] + g_tileoff[d0 >> 9] + rk.x;
    __stcs(&g_ssrc[p0], s0);
    int p1 = g_rowstart[d1] + g_tileoff[d1 >> 9] + rk.y;
    __stcs(&g_ssrc[p1], s1);
}

// ---------------- k1: layer1 node GEMM (4 nodes per warp, W in regs) -----------
__global__ void __launch_bounds__(256) k1(const float* __restrict__ x,
                                          const float* __restrict__ a1s,
                                          const float* __restrict__ a1d) {
    int lane = threadIdx.x & 31;
    int warp = (blockIdx.x * 256 + threadIdx.x) >> 5;   // 3125 blocks -> 25000 warps
    int node0 = warp * 4;

    float4 w[10];
#pragma unroll
    for (int j = 0; j < 10; j++)
        w[j] = *(const float4*)(&g_W1T[j][lane * 4]);

#pragma unroll
    for (int n = 0; n < 4; n++) {
        int node = node0 + n;
        float4 xv = __ldcs((const float4*)(x + (size_t)node * IN_CH + lane * 4));
        float acc[10];
#pragma unroll
        for (int j = 0; j < 10; j++)
            acc[j] = xv.x * w[j].x + xv.y * w[j].y + xv.z * w[j].z + xv.w * w[j].w;
#pragma unroll
        for (int j = 0; j < 10; j++)
#pragma unroll
            for (int o = 16; o; o >>= 1)
                acc[j] += __shfl_xor_sync(0xffffffffu, acc[j], o);

        if (lane == 0) {
            float as0 = 0.f, as1v = 0.f, ad0 = 0.f, ad1v = 0.f;
#pragma unroll
            for (int c = 0; c < 5; c++) {
                as0  += acc[c]     * a1s[c];
                as1v += acc[5 + c] * a1s[5 + c];
                ad0  += acc[c]     * a1d[c];
                ad1v += acc[5 + c] * a1d[5 + c];
            }
            ((float2*)g_ad1)[node] = make_float2(ad0, ad1v);
            uint4 a, b;
            a.x = __float_as_uint(as0);
            a.y = __float_as_uint(as1v);
            a.z = h2u(__floats2half2_rn(acc[0], acc[1]));
            a.w = h2u(__floats2half2_rn(acc[2], acc[3]));
            b.x = h2u(__floats2half2_rn(acc[4], acc[5]));
            b.y = h2u(__floats2half2_rn(acc[6], acc[7]));
            b.z = h2u(__floats2half2_rn(acc[8], acc[9]));
            b.w = 0u;
            uint4* rp = (uint4*)(g_rec1 + (size_t)node * 8);
            rp[0] = a;
            rp[1] = b;
        }
    }
}

// ---------------- kedge1: lane-pair gather, 2 loads in flight (R11) ------------
__global__ void kedge1(const float* __restrict__ b1) {
    int lane = threadIdx.x & 31;
    int pairIdx = lane >> 1;
    int isOdd = lane & 1;
    int d = (blockIdx.x * 256 + threadIdx.x) >> 5;   // < NN exactly
    int rs = g_rowstart[d] + g_tileoff[d >> 9];
    int re = g_rowstart[d + 1] + g_tileoff[(d + 1) >> 9];
    float2 ad = ((const float2*)g_ad1)[d];

    float acc[12];
#pragma unroll
    for (int j = 0; j < 12; j++) acc[j] = 0.f;

    // virtual self-loop at rs-1; 32 edges per warp step, 2 loads in flight
    for (int base = rs - 1; base < re; base += 32) {
        int j0 = base + pairIdx;
        int j1 = j0 + 16;
        bool ok0 = (j0 < re);
        bool ok1 = (j1 < re);
        int s0 = (ok0 && j0 >= rs) ? g_ssrc[j0] : d;
        int s1 = ok1 ? g_ssrc[j1] : d;
        uint4 v0 = ((const uint4*)(g_rec1 + (size_t)s0 * 8))[isOdd];
        uint4 v1 = ((const uint4*)(g_rec1 + (size_t)s1 * 8))[isOdd];
        float x00 = __expf(lrelu(__uint_as_float(v0.x) + ad.x));
        float x01 = __expf(lrelu(__uint_as_float(v0.y) + ad.y));
        float x10 = __expf(lrelu(__uint_as_float(v1.x) + ad.x));
        float x11 = __expf(lrelu(__uint_as_float(v1.y) + ad.y));
        x00 = __shfl_sync(0xffffffffu, x00, lane & ~1);
        x01 = __shfl_sync(0xffffffffu, x01, lane & ~1);
        x10 = __shfl_sync(0xffffffffu, x10, lane & ~1);
        x11 = __shfl_sync(0xffffffffu, x11, lane & ~1);
        if (ok0) {
            if (!isOdd) {
                float2 f01 = __half22float2(u2h(v0.z));
                float2 f23 = __half22float2(u2h(v0.w));
                acc[0] += x00;         acc[1] += x01;
                acc[2] += x00 * f01.x; acc[3] += x00 * f01.y;
                acc[4] += x00 * f23.x; acc[5] += x00 * f23.y;
            } else {
                float2 f45 = __half22float2(u2h(v0.x));
                float2 f67 = __half22float2(u2h(v0.y));
                float2 f89 = __half22float2(u2h(v0.z));
                acc[6] += x00 * f45.x;  acc[7] += x01 * f45.y;
                acc[8] += x01 * f67.x;  acc[9] += x01 * f67.y;
                acc[10] += x01 * f89.x; acc[11] += x01 * f89.y;
            }
        }
        if (ok1) {
            if (!isOdd) {
                float2 f01 = __half22float2(u2h(v1.z));
                float2 f23 = __half22float2(u2h(v1.w));
                acc[0] += x10;         acc[1] += x11;
                acc[2] += x10 * f01.x; acc[3] += x10 * f01.y;
                acc[4] += x10 * f23.x; acc[5] += x10 * f23.y;
            } else {
                float2 f45 = __half22float2(u2h(v1.x));
                float2 f67 = __half22float2(u2h(v1.y));
                float2 f89 = __half22float2(u2h(v1.z));
                acc[6] += x10 * f45.x;  acc[7] += x11 * f45.y;
                acc[8] += x11 * f67.x;  acc[9] += x11 * f67.y;
                acc[10] += x11 * f89.x; acc[11] += x11 * f89.y;
            }
        }
    }
#pragma unroll
    for (int k = 0; k < 12; k++)
#pragma unroll
        for (int o = 16; o; o >>= 1)
            acc[k] += __shfl_xor_sync(0xffffffffu, acc[k], o);

    if (lane == 0) {
        float i0 = 1.f / (acc[0] + 1e-16f);
        float i1 = 1.f / (acc[1] + 1e-16f);
        float2* tp = (float2*)(g_t1 + (size_t)d * 10);
        tp[0] = make_float2(acc[2] * i0 + b1[0], acc[3] * i0 + b1[1]);
        tp[1] = make_float2(acc[4] * i0 + b1[2], acc[5] * i0 + b1[3]);
        tp[2] = make_float2(acc[6] * i0 + b1[4], acc[7] * i1 + b1[5]);
        tp[3] = make_float2(acc[8] * i1 + b1[6], acc[9] * i1 + b1[7]);
        tp[4] = make_float2(acc[10] * i1 + b1[8], acc[11] * i1 + b1[9]);
    }
}

// ---------------- kbn: BN statistics -------------------------------------------
__global__ void kbn() {
    __shared__ double ssum[10], ssq[10];
    if (threadIdx.x < 10) { ssum[threadIdx.x] = 0.0; ssq[threadIdx.x] = 0.0; }
    __syncthreads();
    int node = blockIdx.x * blockDim.x + threadIdx.x;
    int lane = threadIdx.x & 31;
    float t[10];
    if (node < NN) {
        const float2* tp = (const float2*)(g_t1 + (size_t)node * 10);
#pragma unroll
        for (int c = 0; c < 5; c++) {
            float2 v = tp[c];
            t[2 * c] = v.x;
            t[2 * c + 1] = v.y;
        }
    } else {
#pragma unroll
        for (int j = 0; j < 10; j++) t[j] = 0.f;
    }
#pragma unroll
    for (int j = 0; j < 10; j++) {
        float v = t[j];
        float s = t[j] * t[j];
#pragma unroll
        for (int o = 16; o; o >>= 1) {
            v += __shfl_xor_sync(0xffffffffu, v, o);
            s += __shfl_xor_sync(0xffffffffu, s, o);
        }
        if (lane == 0) {
            atomicAdd(&ssum[j], (double)v);
            atomicAdd(&ssq[j], (double)s);
        }
    }
    __syncthreads();
    if (threadIdx.x < 10) {
        atomicAdd(&g_bnsum[threadIdx.x], ssum[threadIdx.x]);
        atomicAdd(&g_bnsumsq[threadIdx.x], ssq[threadIdx.x]);
    }
}

// ---------------- k5: BN const + apply + ELU + layer2 node GEMM ----------------
__global__ void k5(const float* __restrict__ W2, const float* __restrict__ a2s,
                   const float* __restrict__ a2d, const float* __restrict__ gamma,
                   const float* __restrict__ beta) {
    __shared__ float sW[100], sa[10], sd[10], ssc[10], ssh[10];
    if (threadIdx.x < 100) sW[threadIdx.x] = W2[threadIdx.x];
    if (threadIdx.x < 10) {
        sa[threadIdx.x] = a2s[threadIdx.x];
        sd[threadIdx.x] = a2d[threadIdx.x];
        double mean = g_bnsum[threadIdx.x] / (double)NN;
        double var = g_bnsumsq[threadIdx.x] / (double)NN - mean * mean;
        float sc = gamma[threadIdx.x] * (float)rsqrt(var + 1e-5);
        ssc[threadIdx.x] = sc;
        ssh[threadIdx.x] = beta[threadIdx.x] - (float)mean * sc;
    }
    __syncthreads();
    int node = blockIdx.x * blockDim.x + threadIdx.x;
    if (node >= NN) return;

    float y[10];
    const float2* tp = (const float2*)(g_t1 + (size_t)node * 10);
#pragma unroll
    for (int c = 0; c < 5; c++) {
        float2 v = tp[c];
        float u0 = v.x * ssc[2 * c] + ssh[2 * c];
        float u1 = v.y * ssc[2 * c + 1] + ssh[2 * c + 1];
        y[2 * c]     = u0 > 0.f ? u0 : expm1f(u0);
        y[2 * c + 1] = u1 > 0.f ? u1 : expm1f(u1);
    }
    float h[10];
#pragma unroll
    for (int c = 0; c < 10; c++) {
        float s = 0.f;
#pragma unroll
        for (int jj = 0; jj < 10; jj++) s += y[jj] * sW[jj * 10 + c];
        h[c] = s;
    }
    float as = 0.f, ad = 0.f;
#pragma unroll
    for (int c = 0; c < 10; c++) {
        as += h[c] * sa[c];
        ad += h[c] * sd[c];
    }
    g_ad2[node] = ad;
    uint4 a, b;
    a.x = __float_as_uint(as);
    a.y = h2u(__floats2half2_rn(h[0], h[1]));
    a.z = h2u(__floats2half2_rn(h[2], h[3]));
    a.w = h2u(__floats2half2_rn(h[4], h[5]));
    b.x = h2u(__floats2half2_rn(h[6], h[7]));
    b.y = h2u(__floats2half2_rn(h[8], h[9]));
    b.z = 0u; b.w = 0u;
    uint4* rp = (uint4*)(g_rec2 + (size_t)node * 8);
    rp[0] = a;
    rp[1] = b;
}

// ---------------- kedge2: lane-pair gather, 2 loads in flight -> output (R11) --
__global__ void kedge2(float* __restrict__ out, const float* __restrict__ b2) {
    int gtid = blockIdx.x * 256 + threadIdx.x;
    if (gtid < NN) g_deg[gtid] = 0;
    if (gtid < 10) g_bnsum[gtid] = 0.0;
    else if (gtid < 20) g_bnsumsq[gtid - 10] = 0.0;

    int lane = threadIdx.x & 31;
    int pairIdx = lane >> 1;
    int isOdd = lane & 1;
    int d = gtid >> 5;
    int rs = g_rowstart[d] + g_tileoff[d >> 9];
    int re = g_rowstart[d + 1] + g_tileoff[(d + 1) >> 9];
    float ad = g_ad2[d];

    float acc[11];
#pragma unroll
    for (int j = 0; j < 11; j++) acc[j] = 0.f;

    for (int base = rs - 1; base < re; base += 32) {
        int j0 = base + pairIdx;
        int j1 = j0 + 16;
        bool ok0 = (j0 < re);
        bool ok1 = (j1 < re);
        int s0 = (ok0 && j0 >= rs) ? g_ssrc[j0] : d;
        int s1 = ok1 ? g_ssrc[j1] : d;
        uint4 v0 = ((const uint4*)(g_rec2 + (size_t)s0 * 8))[isOdd];
        uint4 v1 = ((const uint4*)(g_rec2 + (size_t)s1 * 8))[isOdd];
        float ex0 = __expf(lrelu(__uint_as_float(v0.x) + ad));
        float ex1 = __expf(lrelu(__uint_as_float(v1.x) + ad));
        ex0 = __shfl_sync(0xffffffffu, ex0, lane & ~1);
        ex1 = __shfl_sync(0xffffffffu, ex1, lane & ~1);
        if (ok0) {
            if (!isOdd) {
                float2 f01 = __half22float2(u2h(v0.y));
                float2 f23 = __half22float2(u2h(v0.z));
                float2 f45 = __half22float2(u2h(v0.w));
                acc[0] += ex0;
                acc[1] += ex0 * f01.x; acc[2] += ex0 * f01.y;
                acc[3] += ex0 * f23.x; acc[4] += ex0 * f23.y;
                acc[5] += ex0 * f45.x; acc[6] += ex0 * f45.y;
            } else {
                float2 f67 = __half22float2(u2h(v0.x));
                float2 f89 = __half22float2(u2h(v0.y));
                acc[7] += ex0 * f67.x; acc[8] += ex0 * f67.y;
                acc[9] += ex0 * f89.x; acc[10] += ex0 * f89.y;
            }
        }
        if (ok1) {
            if (!isOdd) {
                float2 f01 = __half22float2(u2h(v1.y));
                float2 f23 = __half22float2(u2h(v1.z));
                float2 f45 = __half22float2(u2h(v1.w));
                acc[0] += ex1;
                acc[1] += ex1 * f01.x; acc[2] += ex1 * f01.y;
                acc[3] += ex1 * f23.x; acc[4] += ex1 * f23.y;
                acc[5] += ex1 * f45.x; acc[6] += ex1 * f45.y;
            } else {
                float2 f67 = __half22float2(u2h(v1.x));
                float2 f89 = __half22float2(u2h(v1.y));
                acc[7] += ex1 * f67.x; acc[8] += ex1 * f67.y;
                acc[9] += ex1 * f89.x; acc[10] += ex1 * f89.y;
            }
        }
    }
#pragma unroll
    for (int k = 0; k < 11; k++)
#pragma unroll
        for (int o = 16; o; o >>= 1)
            acc[k] += __shfl_xor_sync(0xffffffffu, acc[k], o);

    if (lane == 0) {
        float inv = 1.f / (acc[0] + 1e-16f);
        float* op = out + (size_t)d * 10;
#pragma unroll
        for (int c = 0; c < 10; c++)
            op[c] = acc[1 + c] * inv + b2[c];
    }
}

// ---------------- launch ---------------------------------------------------------
extern "C" void kernel_launch(void* const* d_in, const int* in_sizes, int n_in,
                              void* d_out, int out_size) {
    (void)in_sizes; (void)n_in; (void)out_size;
    const float* x      = (const float*)d_in[0];
    const float* W1     = (const float*)d_in[1];
    const float* a_src1 = (const float*)d_in[2];
    const float* a_dst1 = (const float*)d_in[3];
    const float* b1     = (const float*)d_in[4];
    const float* gamma1 = (const float*)d_in[5];
    const float* beta1  = (const float*)d_in[6];
    const float* W2     = (const float*)d_in[7];
    const float* a_src2 = (const float*)d_in[8];
    const float* a_dst2 = (const float*)d_in[9];
    const float* b2     = (const float*)d_in[10];
    const void*  ei     = d_in[11];

    khist<<<12500, 256>>>(ei, W1);                                    // 0
    kscan1<<<NB, TILE>>>();                                           // 1
    kscan2<<<1, 256>>>();                                             // 2
    kscatter<<<12500, 256>>>(ei);                                     // 3 <- profiled
    k1<<<3125, 256>>>(x, a_src1, a_dst1);                             // 4
    kedge1<<<12500, 256>>>(b1);                                       // 5
    kbn<<<(NN + 255) / 256, 256>>>();                                 // 6
    k5<<<(NN + 255) / 256, 256>>>(W2, a_src2, a_dst2, gamma1, beta1); // 7
    kedge2<<<12500, 256>>>((float*)d_out, b2);                        // 8
}